// round 7
// baseline (speedup 1.0000x reference)
#include <cuda_runtime.h>

#define N_ROWS 2048      // 256 * 8
#define L 128
#define OUT 65
#define OUT2 (OUT * OUT) // 4225
#define EPS 1e-6f

__global__ __launch_bounds__(32) void gasf_kernel(const float* __restrict__ x,
                                                  float* __restrict__ out) {
    __shared__ float2 scss[OUT];               // (cos, sin) per position, 520 B

    const int row = blockIdx.x;                // one (n, c) row per 1-warp block
    const int lane = threadIdx.x;              // 0..31
    const float POS_INF = __int_as_float(0x7f800000);

    // ---- load 128 floats: one float4 per lane, coalesced 512B ----
    float4 v = ((const float4*)(x + row * L))[lane];

    // ---- first/last nonzero via nibble ballot ----
    int nib = (v.x != 0.0f ? 1 : 0) | (v.y != 0.0f ? 2 : 0) |
              (v.z != 0.0f ? 4 : 0) | (v.w != 0.0f ? 8 : 0);
    unsigned m = __ballot_sync(0xffffffffu, nib != 0);

    int first = L, last = -1;
    {
        int lf = __ffs(m) - 1;                         // junk if m==0 (guarded)
        int ll = 31 - __clz(m | 1u);
        int nf = __shfl_sync(0xffffffffu, nib, m ? lf : 0);
        int nl = __shfl_sync(0xffffffffu, nib, m ? ll : 0);
        if (m) {
            first = 4 * lf + (__ffs(nf) - 1);
            last  = 4 * ll + (31 - __clz((unsigned)nl));
        }
    }

    // ---- per-lane masked min/max over 4 elements, then warp reduce ----
    const int p0 = 4 * lane;
    bool val0 = (p0 + 0 >= first) && (p0 + 0 <= last);
    bool val1 = (p0 + 1 >= first) && (p0 + 1 <= last);
    bool val2 = (p0 + 2 >= first) && (p0 + 2 <= last);
    bool val3 = (p0 + 3 >= first) && (p0 + 3 <= last);
    float mn = POS_INF, mx = -POS_INF;
    if (val0) { mn = fminf(mn, v.x); mx = fmaxf(mx, v.x); }
    if (val1) { mn = fminf(mn, v.y); mx = fmaxf(mx, v.y); }
    if (val2) { mn = fminf(mn, v.z); mx = fmaxf(mx, v.z); }
    if (val3) { mn = fminf(mn, v.w); mx = fmaxf(mx, v.w); }
    #pragma unroll
    for (int off = 16; off; off >>= 1) {
        mn = fminf(mn, __shfl_xor_sync(0xffffffffu, mn, off));
        mx = fmaxf(mx, __shfl_xor_sync(0xffffffffu, mx, off));
    }
    float xmin = fminf(mn, 0.0f);              // inf (all-invalid) -> 0, clamp <= 0
    float xmax = fmaxf(mx, 0.0f);
    float inv_range = 2.0f / fmaxf(xmax - xmin, EPS);

    // ---- c,s for positions 0..64 (lanes 0..16) ----
    if (p0 < OUT) {
        float vv[4] = { v.x, v.y, v.z, v.w };
        bool vf[4] = { val0, val1, val2, val3 };
        #pragma unroll
        for (int k = 0; k < 4; ++k) {
            int p = p0 + k;
            if (p < OUT) {
                float xn = vf[k] ? ((vv[k] - xmin) * inv_range - 1.0f) : 0.0f;
                float c = fminf(fmaxf(xn, -1.0f + EPS), 1.0f - EPS);
                float s = sqrtf(fmaxf(1.0f - c * c, 0.0f));
                scss[p] = make_float2(c, s);
            }
        }
    }
    __syncwarp();

    // ---- body: lane owns columns j1=lane, j2=lane+32; lane 31 also j=64 ----
    const float2 b1 = scss[lane];
    const float2 b2 = scss[lane + 32];         // lane+32 in [32,63]
    const float2 b3 = scss[64];
    const float nb1y = -b1.y, nb2y = -b2.y, nb3y = -b3.y;

    float* o = out + (size_t)row * OUT2;
    #pragma unroll
    for (int i = 0; i < OUT; ++i) {
        float2 a = scss[i];                    // LDS.64 broadcast
        o[i * OUT + lane]      = fmaf(a.x, b1.x, a.y * nb1y);
        o[i * OUT + lane + 32] = fmaf(a.x, b2.x, a.y * nb2y);
        if (lane == 31)
            o[i * OUT + 64]    = fmaf(a.x, b3.x, a.y * nb3y);
    }
}

extern "C" void kernel_launch(void* const* d_in, const int* in_sizes, int n_in,
                              void* d_out, int out_size) {
    const float* x = (const float*)d_in[0];
    float* out = (float*)d_out;
    gasf_kernel<<<N_ROWS, 32>>>(x, out);
}

// round 8
// speedup vs baseline: 1.0688x; 1.0688x over previous
#include <cuda_runtime.h>

#define N_ROWS 2048      // 256 * 8
#define L 128
#define OUT 65
#define OUT2 (OUT * OUT) // 4225
#define WARPS_PER_BLK 4
#define EPS 1e-6f

// Each 32-thread warp is an independent unit: (row, half). half=0 -> i in [0,32],
// half=1 -> i in [33,64]. Preamble is duplicated per warp (cheap) so there is
// zero cross-warp coupling: no __syncthreads anywhere.
__global__ __launch_bounds__(32 * WARPS_PER_BLK) void gasf_kernel(const float* __restrict__ x,
                                                                  float* __restrict__ out) {
    __shared__ float2 scss[WARPS_PER_BLK][OUT];   // per-warp private (cos, sin)

    const int lane = threadIdx.x & 31;
    const int wid = threadIdx.x >> 5;             // 0..3
    const int wuid = blockIdx.x * WARPS_PER_BLK + wid;  // 0..4095
    const int row = wuid >> 1;                    // one (n,c) row per 2 warps
    const int half = wuid & 1;
    const float POS_INF = __int_as_float(0x7f800000);

    // ---- load 128 floats: one float4 per lane, coalesced 512B ----
    float4 v = ((const float4*)(x + row * L))[lane];

    // ---- first/last nonzero via nibble ballot ----
    int nib = (v.x != 0.0f ? 1 : 0) | (v.y != 0.0f ? 2 : 0) |
              (v.z != 0.0f ? 4 : 0) | (v.w != 0.0f ? 8 : 0);
    unsigned m = __ballot_sync(0xffffffffu, nib != 0);

    int first = L, last = -1;
    {
        int lf = __ffs(m) - 1;                     // junk if m==0 (guarded)
        int ll = 31 - __clz(m | 1u);
        int nf = __shfl_sync(0xffffffffu, nib, m ? lf : 0);
        int nl = __shfl_sync(0xffffffffu, nib, m ? ll : 0);
        if (m) {
            first = 4 * lf + (__ffs(nf) - 1);
            last  = 4 * ll + (31 - __clz((unsigned)nl));
        }
    }

    // ---- per-lane masked min/max over 4 elements, then warp reduce ----
    const int p0 = 4 * lane;
    bool val0 = (p0 + 0 >= first) && (p0 + 0 <= last);
    bool val1 = (p0 + 1 >= first) && (p0 + 1 <= last);
    bool val2 = (p0 + 2 >= first) && (p0 + 2 <= last);
    bool val3 = (p0 + 3 >= first) && (p0 + 3 <= last);
    float mn = POS_INF, mx = -POS_INF;
    if (val0) { mn = fminf(mn, v.x); mx = fmaxf(mx, v.x); }
    if (val1) { mn = fminf(mn, v.y); mx = fmaxf(mx, v.y); }
    if (val2) { mn = fminf(mn, v.z); mx = fmaxf(mx, v.z); }
    if (val3) { mn = fminf(mn, v.w); mx = fmaxf(mx, v.w); }
    #pragma unroll
    for (int off = 16; off; off >>= 1) {
        mn = fminf(mn, __shfl_xor_sync(0xffffffffu, mn, off));
        mx = fmaxf(mx, __shfl_xor_sync(0xffffffffu, mx, off));
    }
    float xmin = fminf(mn, 0.0f);              // inf (all-invalid) -> 0, clamp <= 0
    float xmax = fmaxf(mx, 0.0f);
    float inv_range = 2.0f / fmaxf(xmax - xmin, EPS);

    // ---- c,s for positions 0..64 (lanes 0..16 of this warp) ----
    if (p0 < OUT) {
        float vv[4] = { v.x, v.y, v.z, v.w };
        bool vf[4] = { val0, val1, val2, val3 };
        #pragma unroll
        for (int k = 0; k < 4; ++k) {
            int p = p0 + k;
            if (p < OUT) {
                float xn = vf[k] ? ((vv[k] - xmin) * inv_range - 1.0f) : 0.0f;
                float c = fminf(fmaxf(xn, -1.0f + EPS), 1.0f - EPS);
                float s = sqrtf(fmaxf(1.0f - c * c, 0.0f));
                scss[wid][p] = make_float2(c, s);
            }
        }
    }
    __syncwarp();

    // ---- body: lane owns columns j=lane, j=lane+32; lane 31 also j=64 ----
    const float2 b1 = scss[wid][lane];
    const float2 b2 = scss[wid][lane + 32];
    const float2 b3 = scss[wid][64];
    const float nb1y = -b1.y, nb2y = -b2.y, nb3y = -b3.y;

    float* o = out + (size_t)row * OUT2;
    if (half == 0) {
        #pragma unroll
        for (int i = 0; i < 33; ++i) {
            float2 a = scss[wid][i];               // LDS.64 broadcast
            o[i * OUT + lane]      = fmaf(a.x, b1.x, a.y * nb1y);
            o[i * OUT + lane + 32] = fmaf(a.x, b2.x, a.y * nb2y);
            if (lane == 31)
                o[i * OUT + 64]    = fmaf(a.x, b3.x, a.y * nb3y);
        }
    } else {
        #pragma unroll
        for (int i = 33; i < OUT; ++i) {
            float2 a = scss[wid][i];
            o[i * OUT + lane]      = fmaf(a.x, b1.x, a.y * nb1y);
            o[i * OUT + lane + 32] = fmaf(a.x, b2.x, a.y * nb2y);
            if (lane == 31)
                o[i * OUT + 64]    = fmaf(a.x, b3.x, a.y * nb3y);
        }
    }
}

extern "C" void kernel_launch(void* const* d_in, const int* in_sizes, int n_in,
                              void* d_out, int out_size) {
    const float* x = (const float*)d_in[0];
    float* out = (float*)d_out;
    gasf_kernel<<<N_ROWS / 2, 32 * WARPS_PER_BLK>>>(x, out);
}